// round 5
// baseline (speedup 1.0000x reference)
#include <cuda_runtime.h>
#include <cstdint>

#define NN 100000
#define EE 1600000
#define FF 128
#define HH 64
#define GG 128
#define CC 10
#define EPS 1e-5f
#define FULLMASK 0xffffffffu

// ---------------- device scratch (static allocations allowed) ----------------
__device__ __align__(16) float g_h1[NN * HH];
__device__ __align__(16) float g_h2[NN * HH];
__device__ __align__(16) float g_hw[NN * HH];
__device__ int   g_degcnt[NN];
__device__ int   g_counts[NN];
__device__ int   g_offs[NN];
__device__ int   g_cursor[NN];
__device__ float g_dinv[NN];
__device__ int   g_src[EE];
__device__ float g_w[EE];
__device__ int   g_blockSums[256];
__device__ float g_sum[FF];
__device__ float g_sumsq[FF];
__device__ __align__(16) float g_Wp[FF * HH];
__device__ __align__(16) float g_c1[HH];
__device__ __align__(16) float g_Wc[HH * HH];
__device__ __align__(16) float g_c2[HH];
__device__ __align__(16) float g_hg[GG * HH];

// buffer selector helper: 0 -> g_h1, 1 -> g_h2
__device__ __forceinline__ float* buf(int sel) { return sel ? g_h2 : g_h1; }

// ---------------- zero / init ----------------
__global__ void zero_all(int n) {
    int i = blockIdx.x * blockDim.x + threadIdx.x;
    int st = gridDim.x * blockDim.x;
    for (int k = i; k < n; k += st) { g_degcnt[k] = 0; g_counts[k] = 0; }
    for (int k = i; k < GG * HH; k += st) g_hg[k] = 0.f;
}

__global__ void zero_stats() {
    if (threadIdx.x < FF) { g_sum[threadIdx.x] = 0.f; g_sumsq[threadIdx.x] = 0.f; }
}

// ---------------- CSR build (edge_index is int32!) ----------------
__global__ void edge_count(const int* __restrict__ ei, int e) {
    int idx = blockIdx.x * blockDim.x + threadIdx.x;
    if (idx >= e) return;
    int r = ei[idx];
    int c = ei[idx + e];
    if (r != c) {
        atomicAdd(&g_degcnt[r], 1);
        atomicAdd(&g_counts[c], 1);
    }
}

__global__ void compute_dinv(int n) {
    int i = blockIdx.x * blockDim.x + threadIdx.x;
    if (i < n) g_dinv[i] = rsqrtf((float)g_degcnt[i] + 1.0f);
}

__global__ void scan_blocks(int n) {
    __shared__ int tmp[1024];
    int i = blockIdx.x * 1024 + threadIdx.x;
    int v = (i < n) ? g_counts[i] : 0;
    tmp[threadIdx.x] = v;
    __syncthreads();
    for (int d = 1; d < 1024; d <<= 1) {
        int t = (threadIdx.x >= d) ? tmp[threadIdx.x - d] : 0;
        __syncthreads();
        tmp[threadIdx.x] += t;
        __syncthreads();
    }
    if (i < n) g_offs[i] = tmp[threadIdx.x] - v;   // exclusive
    if (threadIdx.x == 1023) g_blockSums[blockIdx.x] = tmp[1023];
}

__global__ void scan_top(int nblk) {
    if (threadIdx.x == 0 && blockIdx.x == 0) {
        int run = 0;
        for (int b = 0; b < nblk; b++) { int t = g_blockSums[b]; g_blockSums[b] = run; run += t; }
    }
}

__global__ void scan_add(int n) {
    int i = blockIdx.x * blockDim.x + threadIdx.x;
    if (i < n) {
        int off = g_offs[i] + g_blockSums[i >> 10];
        g_offs[i] = off;
        g_cursor[i] = off;
    }
}

__global__ void fill_edges(const int* __restrict__ ei, int e) {
    int idx = blockIdx.x * blockDim.x + threadIdx.x;
    if (idx >= e) return;
    int r = ei[idx];
    int c = ei[idx + e];
    if (r != c) {
        int p = atomicAdd(&g_cursor[c], 1);
        g_src[p] = r;
        g_w[p] = g_dinv[r] * g_dinv[c];
    }
}

// ---------------- column stats over external input x (128 cols) ----------------
__global__ void colstats_x(const float* __restrict__ a, int nrows) {
    __shared__ float sh[512];
    const int ncols = FF;
    int col = threadIdx.x % ncols;
    int rl  = threadIdx.x / ncols;
    int rif = blockDim.x / ncols;
    float s = 0.f, q = 0.f;
    for (int row = blockIdx.x * rif + rl; row < nrows; row += gridDim.x * rif) {
        float v = a[(size_t)row * ncols + col];
        s += v; q += v * v;
    }
    sh[threadIdx.x] = s; __syncthreads();
    if (rl == 0) {
        for (int t = 1; t < rif; t++) s += sh[t * ncols + col];
        atomicAdd(&g_sum[col], s);
    }
    __syncthreads();
    sh[threadIdx.x] = q; __syncthreads();
    if (rl == 0) {
        for (int t = 1; t < rif; t++) q += sh[t * ncols + col];
        atomicAdd(&g_sumsq[col], q);
    }
}

// ---------------- column stats over internal buffer (64 cols) ----------------
__global__ void colstats_h(int sel, int nrows) {
    __shared__ float sh[512];
    const float* a = buf(sel);
    const int ncols = HH;
    int col = threadIdx.x % ncols;
    int rl  = threadIdx.x / ncols;
    int rif = blockDim.x / ncols;
    float s = 0.f, q = 0.f;
    for (int row = blockIdx.x * rif + rl; row < nrows; row += gridDim.x * rif) {
        float v = a[(size_t)row * ncols + col];
        s += v; q += v * v;
    }
    sh[threadIdx.x] = s; __syncthreads();
    if (rl == 0) {
        for (int t = 1; t < rif; t++) s += sh[t * ncols + col];
        atomicAdd(&g_sum[col], s);
    }
    __syncthreads();
    sh[threadIdx.x] = q; __syncthreads();
    if (rl == 0) {
        for (int t = 1; t < rif; t++) q += sh[t * ncols + col];
        atomicAdd(&g_sumsq[col], q);
    }
}

// ---------------- BN-fold weight prep ----------------
__global__ void prep_feat(const float* __restrict__ Wf, const float* __restrict__ g,
                          const float* __restrict__ b, float inv_n) {
    __shared__ float scale[FF], beta[FF];
    int t = threadIdx.x;
    if (t < FF) {
        float m = g_sum[t] * inv_n;
        float v = g_sumsq[t] * inv_n - m * m;
        float s = rsqrtf(v + EPS) * g[t];
        scale[t] = s;
        beta[t]  = b[t] - m * s;
    }
    __syncthreads();
    for (int i = t; i < FF * HH; i += blockDim.x) g_Wp[i] = scale[i / HH] * Wf[i];
    if (t < HH) {
        float c = 0.f;
        for (int k = 0; k < FF; k++) c += beta[k] * Wf[k * HH + t];
        g_c1[t] = c;
    }
}

__global__ void prep_conv(const float* __restrict__ Wc, const float* __restrict__ g,
                          const float* __restrict__ b, float inv_n) {
    __shared__ float scale[HH], beta[HH];
    int t = threadIdx.x;
    if (t < HH) {
        float m = g_sum[t] * inv_n;
        float v = g_sumsq[t] * inv_n - m * m;
        float s = rsqrtf(v + EPS) * g[t];
        scale[t] = s;
        beta[t]  = b[t] - m * s;
    }
    __syncthreads();
    for (int i = t; i < HH * HH; i += blockDim.x) g_Wc[i] = scale[i / HH] * Wc[i];
    if (t < HH) {
        float c = 0.f;
        for (int k = 0; k < HH; k++) c += beta[k] * Wc[k * HH + t];
        g_c2[t] = c;
    }
}

// ---------------- matmuls: warp computes 4 rows, lane -> 2 output cols ----------------
__global__ void mm_feat(const float* __restrict__ x, int osel, int n) {
    __shared__ float2 ws[FF * 32];
    __shared__ float2 cs[32];
    float* out = buf(osel);
    for (int i = threadIdx.x; i < FF * 32; i += blockDim.x)
        ws[i] = ((const float2*)g_Wp)[i];
    if (threadIdx.x < 32) cs[threadIdx.x] = ((const float2*)g_c1)[threadIdx.x];
    __syncthreads();

    int lane = threadIdx.x & 31;
    int warp = (blockIdx.x * blockDim.x + threadIdx.x) >> 5;
    int r0 = warp * 4;
    if (r0 >= n) return;

    float xr[4][4];
#pragma unroll
    for (int rr = 0; rr < 4; rr++) {
        int row = min(r0 + rr, n - 1);
        const float* xp = x + (size_t)row * FF;
#pragma unroll
        for (int kk = 0; kk < 4; kk++) xr[rr][kk] = xp[kk * 32 + lane];
    }
    float2 c = cs[lane];
    float2 acc[4];
#pragma unroll
    for (int rr = 0; rr < 4; rr++) acc[rr] = c;

#pragma unroll
    for (int kk = 0; kk < 4; kk++) {
        for (int j = 0; j < 32; j++) {
            float2 w = ws[(kk * 32 + j) * 32 + lane];
#pragma unroll
            for (int rr = 0; rr < 4; rr++) {
                float xv = __shfl_sync(FULLMASK, xr[rr][kk], j);
                acc[rr].x += xv * w.x;
                acc[rr].y += xv * w.y;
            }
        }
    }
#pragma unroll
    for (int rr = 0; rr < 4; rr++) {
        int row = r0 + rr;
        if (row < n) {
            float2 o;
            o.x = fmaxf(acc[rr].x, 0.f);
            o.y = fmaxf(acc[rr].y, 0.f);
            ((float2*)out)[(size_t)row * 32 + lane] = o;
        }
    }
}

__global__ void mm_conv(int isel, int n) {
    __shared__ float2 ws[HH * 32];
    __shared__ float2 cs[32];
    const float* in = buf(isel);
    float* out = g_hw;
    for (int i = threadIdx.x; i < HH * 32; i += blockDim.x)
        ws[i] = ((const float2*)g_Wc)[i];
    if (threadIdx.x < 32) cs[threadIdx.x] = ((const float2*)g_c2)[threadIdx.x];
    __syncthreads();

    int lane = threadIdx.x & 31;
    int warp = (blockIdx.x * blockDim.x + threadIdx.x) >> 5;
    int r0 = warp * 4;
    if (r0 >= n) return;

    float xr[4][2];
#pragma unroll
    for (int rr = 0; rr < 4; rr++) {
        int row = min(r0 + rr, n - 1);
        const float* xp = in + (size_t)row * HH;
#pragma unroll
        for (int kk = 0; kk < 2; kk++) xr[rr][kk] = xp[kk * 32 + lane];
    }
    float2 c = cs[lane];
    float2 acc[4];
#pragma unroll
    for (int rr = 0; rr < 4; rr++) acc[rr] = c;

#pragma unroll
    for (int kk = 0; kk < 2; kk++) {
        for (int j = 0; j < 32; j++) {
            float2 w = ws[(kk * 32 + j) * 32 + lane];
#pragma unroll
            for (int rr = 0; rr < 4; rr++) {
                float xv = __shfl_sync(FULLMASK, xr[rr][kk], j);
                acc[rr].x += xv * w.x;
                acc[rr].y += xv * w.y;
            }
        }
    }
#pragma unroll
    for (int rr = 0; rr < 4; rr++) {
        int row = r0 + rr;
        if (row < n)
            ((float2*)out)[(size_t)row * 32 + lane] = acc[rr];   // linear (pre-aggregation)
    }
}

// ---------------- CSR pull aggregation: warp per destination node ----------------
__global__ void aggregate(int osel, const float* __restrict__ bias, int n) {
    int lane = threadIdx.x & 31;
    int v = (blockIdx.x * blockDim.x + threadIdx.x) >> 5;
    if (v >= n) return;

    float* out = buf(osel);
    const float2* hw2 = (const float2*)g_hw;
    float dv = g_dinv[v];
    float sl = dv * dv;                     // self-loop weight = 1/deg
    float2 hs = hw2[(size_t)v * 32 + lane];
    float ax = hs.x * sl, ay = hs.y * sl;

    int s = g_offs[v];
    int cnt = g_counts[v];
    for (int base = 0; base < cnt; base += 32) {
        int nIdx = 0; float w = 0.f;
        if (base + lane < cnt) {
            nIdx = g_src[s + base + lane];
            w    = g_w[s + base + lane];
        }
        int m = min(32, cnt - base);
        for (int j = 0; j < m; j++) {
            int   srcn = __shfl_sync(FULLMASK, nIdx, j);
            float ww   = __shfl_sync(FULLMASK, w, j);
            float2 hv = hw2[(size_t)srcn * 32 + lane];
            ax += ww * hv.x;
            ay += ww * hv.y;
        }
    }
    float b0 = bias[2 * lane], b1 = bias[2 * lane + 1];
    float2 o;
    o.x = fmaxf(ax + b0, 0.f);
    o.y = fmaxf(ay + b1, 0.f);
    ((float2*)out)[(size_t)v * 32 + lane] = o;
}

// ---------------- pooling: thread = column, run-length accumulate over sorted batch ----------------
#define POOL_CHUNK 128
__global__ void pool_kernel(int isel, const int* __restrict__ batch, int n) {
    const float* h = buf(isel);
    int j = threadIdx.x;                     // 0..63
    int start = blockIdx.x * POOL_CHUNK;
    int end = min(start + POOL_CHUNK, n);
    if (start >= end) return;
    int cur = batch[start];
    float acc = 0.f;
    for (int r = start; r < end; r++) {
        int gid = batch[r];
        if (gid != cur) {
            atomicAdd(&g_hg[cur * HH + j], acc);
            acc = 0.f;
            cur = gid;
        }
        acc += h[(size_t)r * HH + j];
    }
    atomicAdd(&g_hg[cur * HH + j], acc);
}

// ---------------- head: BN -> fc+relu -> BN -> classifier (single block) ----------------
__global__ void head_kernel(const float* __restrict__ Wfc, const float* __restrict__ bfc,
                            const float* __restrict__ Wcls, const float* __restrict__ bcls,
                            const float* __restrict__ fg, const float* __restrict__ fb,
                            const float* __restrict__ hg, const float* __restrict__ hb,
                            float* __restrict__ out) {
    __shared__ float sh[GG * HH];
    __shared__ float mcol[HH], rcol[HH];
    int t = threadIdx.x;

    for (int i = t; i < GG * HH; i += blockDim.x) sh[i] = g_hg[i];
    __syncthreads();

    if (t < HH) {
        float s = 0.f, q = 0.f;
        for (int r = 0; r < GG; r++) { float v = sh[r * HH + t]; s += v; q += v * v; }
        float m = s / (float)GG;
        float var = q / (float)GG - m * m;
        mcol[t] = m; rcol[t] = rsqrtf(var + EPS);
    }
    __syncthreads();
    for (int i = t; i < GG * HH; i += blockDim.x) {
        int c = i & (HH - 1);
        sh[i] = (sh[i] - mcol[c]) * rcol[c] * fg[c] + fb[c];
    }
    __syncthreads();

    // fc: thread handles (row = t&127, 32 cols)
    float y[32];
    int r = t & 127;
    int j0 = (t >> 7) * 32;
    for (int jj = 0; jj < 32; jj++) {
        float a = bfc[j0 + jj];
        for (int k = 0; k < HH; k++) a += sh[r * HH + k] * Wfc[k * HH + j0 + jj];
        y[jj] = fmaxf(a, 0.f);
    }
    __syncthreads();
    for (int jj = 0; jj < 32; jj++) sh[r * HH + j0 + jj] = y[jj];
    __syncthreads();

    if (t < HH) {
        float s = 0.f, q = 0.f;
        for (int rr = 0; rr < GG; rr++) { float v = sh[rr * HH + t]; s += v; q += v * v; }
        float m = s / (float)GG;
        float var = q / (float)GG - m * m;
        mcol[t] = m; rcol[t] = rsqrtf(var + EPS);
    }
    __syncthreads();
    for (int i = t; i < GG * HH; i += blockDim.x) {
        int c = i & (HH - 1);
        sh[i] = (sh[i] - mcol[c]) * rcol[c] * hg[c] + hb[c];
    }
    __syncthreads();

    if (t < GG) {
        for (int c = 0; c < CC; c++) {
            float a = bcls[c];
            for (int k = 0; k < HH; k++) a += sh[t * HH + k] * Wcls[k * CC + c];
            out[t * CC + c] = a;
        }
    }
}

// ---------------- host ----------------
extern "C" void kernel_launch(void* const* d_in, const int* in_sizes, int n_in,
                              void* d_out, int out_size) {
    const float* x     = (const float*)d_in[0];
    const int*   ei    = (const int*)d_in[1];     // int32 (JAX default: no x64)
    const int*   batch = (const int*)d_in[2];     // int32

    // 15 parameter tensors come last; num_graphs may or may not be a device
    // input, so index relative to the end.
    int base = n_in - 15;
    const float*     W_feat  = (const float*)d_in[base + 0];
    const float*     W_conv  = (const float*)d_in[base + 1];
    const float*     b_conv  = (const float*)d_in[base + 2];
    const float*     W_fc    = (const float*)d_in[base + 3];
    const float*     b_fc    = (const float*)d_in[base + 4];
    const float*     W_cls   = (const float*)d_in[base + 5];
    const float*     b_cls   = (const float*)d_in[base + 6];
    const float*     bnf_g   = (const float*)d_in[base + 7];
    const float*     bnf_b   = (const float*)d_in[base + 8];
    const float*     bnc_g   = (const float*)d_in[base + 9];
    const float*     bnc_b   = (const float*)d_in[base + 10];
    const float*     bnfc_g  = (const float*)d_in[base + 11];
    const float*     bnfc_b  = (const float*)d_in[base + 12];
    const float*     bnh_g   = (const float*)d_in[base + 13];
    const float*     bnh_b   = (const float*)d_in[base + 14];
    float* out = (float*)d_out;

    int n = in_sizes[0] / FF;     // 100000
    int e = in_sizes[1] / 2;      // 1600000
    float inv_n = 1.0f / (float)n;

    // --- CSR build + degree norms ---
    zero_all<<<512, 256>>>(n);
    edge_count<<<(e + 255) / 256, 256>>>(ei, e);
    compute_dinv<<<(n + 255) / 256, 256>>>(n);
    int nblk = (n + 1023) / 1024;
    scan_blocks<<<nblk, 1024>>>(n);
    scan_top<<<1, 32>>>(nblk);
    scan_add<<<(n + 255) / 256, 256>>>(n);
    fill_edges<<<(e + 255) / 256, 256>>>(ei, e);

    // --- feat stage: BN(x) folded into x @ W_feat, relu -> g_h1 ---
    zero_stats<<<1, 128>>>();
    colstats_x<<<256, 512>>>(x, n);
    prep_feat<<<1, 128>>>(W_feat, bnf_g, bnf_b, inv_n);
    int warps = (n + 3) / 4;
    int mmblocks = (warps + 7) / 8;
    mm_feat<<<mmblocks, 256>>>(x, /*osel=*/0, n);

    // --- 3 GCN layers (ping-pong: 0->1, 1->0, 0->1) ---
    int cur = 0;
    for (int i = 0; i < 3; i++) {
        int nxt = cur ^ 1;
        zero_stats<<<1, 128>>>();
        colstats_h<<<256, 512>>>(cur, n);
        prep_conv<<<1, 128>>>(W_conv + i * HH * HH, bnc_g + i * HH, bnc_b + i * HH, inv_n);
        mm_conv<<<mmblocks, 256>>>(cur, n);
        aggregate<<<(n + 7) / 8, 256>>>(nxt, b_conv + i * HH, n);
        cur = nxt;
    }

    // --- pool + head (final cur == 1 -> g_h2) ---
    pool_kernel<<<(n + POOL_CHUNK - 1) / POOL_CHUNK, HH>>>(cur, batch, n);
    head_kernel<<<1, 256>>>(W_fc, b_fc, W_cls, b_cls,
                            bnfc_g, bnfc_b, bnh_g, bnh_b, out);
}